// round 2
// baseline (speedup 1.0000x reference)
#include <cuda_runtime.h>
#include <cuda_fp16.h>
#include <cuda_bf16.h>
#include <mma.h>
#include <math.h>

using namespace nvcuda;

// ---------------- static config ----------------
#define T_TOK   2048
#define HID     2048
#define MOE_I   1024
#define SH_I    4096
#define NEXP    16
#define MAX_TILES 48              // worst-case sum of ceil(cnt_e/128) is 47
#define MAX_ROWS (MAX_TILES*128)  // 6144 padded assignment rows

// ---------------- device scratch (static, zero-initialized) ----------------
__device__ int    g_topk_idx[T_TOK*2];
__device__ float  g_topk_w[T_TOK*2];
__device__ int    g_cnt[NEXP];
__device__ int    g_off[NEXP];
__device__ int    g_ntiles;
__device__ int    g_tileE[MAX_TILES];
__device__ int    g_tileM0[MAX_TILES];
__device__ int    g_perm[MAX_ROWS];
__device__ float  g_pw[MAX_ROWS];
__device__ __half g_X16[(size_t)T_TOK*HID];      // tokens in fp16 (shared expert A)
__device__ __half g_XG[(size_t)MAX_ROWS*HID];    // gathered tokens per assignment
__device__ __half g_Act[(size_t)MAX_ROWS*MOE_I]; // routed up activations (fp16)
__device__ __half g_ActS[(size_t)T_TOK*SH_I];    // shared up activations (fp16)

// ---------------- router: fp32, exact replica of reference routing ----------------
__global__ __launch_bounds__(128) void router_kernel(
    const float* __restrict__ x, const float* __restrict__ wr,
    const float* __restrict__ eb)
{
    int warp = threadIdx.x >> 5;
    int lane = threadIdx.x & 31;
    int t = blockIdx.x * 4 + warp;
    const float* xr = x + (size_t)t * HID;

    float xv[64];
#pragma unroll
    for (int i = 0; i < 64; i++) xv[i] = xr[lane + 32 * i];

    float sc[NEXP];
#pragma unroll
    for (int e = 0; e < NEXP; e++) {
        const float* w = wr + (size_t)e * HID;
        float s = 0.f;
#pragma unroll
        for (int i = 0; i < 64; i++) s += xv[i] * w[lane + 32 * i];
#pragma unroll
        for (int o = 16; o > 0; o >>= 1) s += __shfl_xor_sync(0xffffffffu, s, o);
        sc[e] = s;
    }

    if (lane == 0) {
        float raw[NEXP], sb[NEXP];
#pragma unroll
        for (int e = 0; e < NEXP; e++) {
            raw[e] = 1.f / (1.f + expf(-sc[e]));
            sb[e]  = raw[e] + eb[e];
        }
        // group scores: sum of top-2 within each group of 4
        float gs[4];
#pragma unroll
        for (int g = 0; g < 4; g++) {
            float m1 = -1e30f, m2 = -1e30f;
#pragma unroll
            for (int j = 0; j < 4; j++) {
                float v = sb[4 * g + j];
                if (v > m1) { m2 = m1; m1 = v; }
                else if (v > m2) m2 = v;
            }
            gs[g] = m1 + m2;
        }
        // top-2 groups (lowest index wins ties, like jax top_k)
        int g1 = 0;
        for (int g = 1; g < 4; g++) if (gs[g] > gs[g1]) g1 = g;
        int g2 = -1;
        for (int g = 0; g < 4; g++) if (g != g1 && (g2 < 0 || gs[g] > gs[g2])) g2 = g;
        // mask and top-2 experts
        float masked[NEXP];
#pragma unroll
        for (int e = 0; e < NEXP; e++) {
            int grp = e >> 2;
            masked[e] = (grp == g1 || grp == g2) ? sb[e] : 0.f;
        }
        int e1 = 0;
        for (int e = 1; e < NEXP; e++) if (masked[e] > masked[e1]) e1 = e;
        int e2 = -1;
        for (int e = 0; e < NEXP; e++) if (e != e1 && (e2 < 0 || masked[e] > masked[e2])) e2 = e;

        float w1 = raw[e1], w2 = raw[e2];
        float s = w1 + w2 + 1e-20f;
        g_topk_idx[t * 2 + 0] = e1;
        g_topk_idx[t * 2 + 1] = e2;
        g_topk_w[t * 2 + 0]   = w1 / s;
        g_topk_w[t * 2 + 1]   = w2 / s;
    }
}

// ---------------- scan: counts, padded offsets, tile table ----------------
__global__ void scan_kernel()
{
    __shared__ int cnt[NEXP];
    int e = threadIdx.x;
    if (e < NEXP) {
        int c = 0;
        for (int i = 0; i < T_TOK * 2; i++) c += (g_topk_idx[i] == e);
        cnt[e] = c;
    }
    __syncthreads();
    if (threadIdx.x == 0) {
        int off = 0, nt = 0;
        for (int ee = 0; ee < NEXP; ee++) {
            g_off[ee] = off;
            g_cnt[ee] = cnt[ee];
            int tiles = (cnt[ee] + 127) / 128;
            for (int tt = 0; tt < tiles; tt++) {
                g_tileE[nt]  = ee;
                g_tileM0[nt] = off + tt * 128;
                nt++;
            }
            off += tiles * 128;
        }
        g_ntiles = nt;
        for (int i = nt; i < MAX_TILES; i++) { g_tileE[i] = -1; g_tileM0[i] = 0; }
    }
}

// ---------------- gather: deterministic ordered compaction per expert ----------------
__global__ __launch_bounds__(256) void gather_kernel()
{
    int e = blockIdx.x;
    int base = g_off[e];
    int tid = threadIdx.x, lane = tid & 31, wid = tid >> 5;
    __shared__ int warpTot[8];
    int written = 0;

    for (int chunk = 0; chunk < T_TOK; chunk += 256) {
        int t = chunk + tid;
        int i0 = g_topk_idx[t * 2], i1 = g_topk_idx[t * 2 + 1];
        int which = (i0 == e) ? 0 : ((i1 == e) ? 1 : -1);
        unsigned b = __ballot_sync(0xffffffffu, which >= 0);
        int wpre = __popc(b & ((1u << lane) - 1));
        if (lane == 0) warpTot[wid] = __popc(b);
        __syncthreads();
        int woff = 0;
        for (int w = 0; w < wid; w++) woff += warpTot[w];
        if (which >= 0) {
            int pos = base + written + woff + wpre;
            g_perm[pos] = t;
            g_pw[pos]   = g_topk_w[t * 2 + which];
        }
        int tot = 0;
        for (int w = 0; w < 8; w++) tot += warpTot[w];
        written += tot;
        __syncthreads();
    }
    // pad the segment to a multiple of 128 rows with weight-0 dummies
    int padEnd = base + ((written + 127) / 128) * 128;
    for (int i = base + written + tid; i < padEnd; i += 256) {
        g_perm[i] = 0;
        g_pw[i]   = 0.f;
    }
}

// ---------------- fp32 -> fp16 row converters ----------------
__device__ __forceinline__ void cvt8(const float* __restrict__ src, __half* __restrict__ dst)
{
    float4 a = *(const float4*)src;
    float4 b = *(const float4*)(src + 4);
    __half2* d = (__half2*)dst;
    d[0] = __floats2half2_rn(a.x, a.y);
    d[1] = __floats2half2_rn(a.z, a.w);
    d[2] = __floats2half2_rn(b.x, b.y);
    d[3] = __floats2half2_rn(b.z, b.w);
}

__global__ __launch_bounds__(256) void convx_kernel(const float* __restrict__ x)
{
    int row = blockIdx.x;
    int c0 = threadIdx.x * 8;
    cvt8(x + (size_t)row * HID + c0, g_X16 + (size_t)row * HID + c0);
}

__global__ __launch_bounds__(256) void gatherx_kernel(const float* __restrict__ x)
{
    int row = blockIdx.x;
    int t = g_perm[row];
    int c0 = threadIdx.x * 8;
    cvt8(x + (size_t)t * HID + c0, g_XG + (size_t)row * HID + c0);
}

// ---------------- unified wmma GEMM ----------------
// MODE 0: shared up   : X16[2048,2048]  x su[2048,4096] -> relu^2 -> ActS (fp16)
// MODE 1: shared down : ActS[2048,4096] x sd[4096,2048] -> out (store fp32)
// MODE 2: routed up   : XG[rows,2048]   x wu[e][2048,1024] -> relu^2 * pw -> Act (fp16)
// MODE 3: routed down : Act[rows,1024]  x wd[e][1024,2048] -> atomicAdd out
template<int MODE>
__global__ __launch_bounds__(256) void gemm_kernel(const float* __restrict__ W,
                                                   float* __restrict__ out)
{
    constexpr int K = (MODE == 0 || MODE == 2) ? 2048 : (MODE == 1 ? 4096 : 1024);
    constexpr int N = (MODE == 0) ? 4096 : (MODE == 2 ? 1024 : 2048);

    int m0;
    const float* Bm;
    if (MODE == 2 || MODE == 3) {
        int tile = blockIdx.y;
        if (tile >= g_ntiles) return;
        m0 = g_tileM0[tile];
        int e = g_tileE[tile];
        Bm = W + (size_t)e * HID * MOE_I;  // both wu and wd per-expert blocks are H*I elems
    } else {
        m0 = blockIdx.y * 128;
        Bm = W;
    }
    int n0 = blockIdx.x * 64;

    const __half* A;
    if (MODE == 0) A = g_X16 + (size_t)m0 * HID;
    if (MODE == 1) A = g_ActS + (size_t)m0 * SH_I;
    if (MODE == 2) A = g_XG  + (size_t)m0 * HID;
    if (MODE == 3) A = g_Act + (size_t)m0 * MOE_I;

    __shared__ __align__(16) float smem_f[128 * 68];     // 34816 B, reused as C
    __half* As = (__half*)smem_f;                         // 128 x 48 halves (12288 B)
    __half* Bs = (__half*)((char*)smem_f + 12288);        // 32 x 72 halves (4608 B)
    float*  Cs = smem_f;

    int tid = threadIdx.x;
    int wid = tid >> 5, wm = wid >> 1, wn = wid & 1;

    wmma::fragment<wmma::accumulator, 16, 16, 16, float> acc[2][2];
#pragma unroll
    for (int i = 0; i < 2; i++)
#pragma unroll
        for (int j = 0; j < 2; j++) wmma::fill_fragment(acc[i][j], 0.f);

    for (int k0 = 0; k0 < K; k0 += 32) {
        // load A tile 128x32 (fp16, vectorized)
#pragma unroll
        for (int l = 0; l < 2; l++) {
            int i = tid + l * 256;
            int r = i >> 2, c8 = (i & 3) * 8;
            *(uint4*)(As + r * 48 + c8) =
                *(const uint4*)(A + (size_t)r * K + k0 + c8);
        }
        // load B tile 32x64 (fp32 -> fp16 on the fly)
#pragma unroll
        for (int l = 0; l < 2; l++) {
            int i = tid + l * 256;
            int r = i >> 4, c4 = (i & 15) * 4;
            float4 v = *(const float4*)(Bm + (size_t)(k0 + r) * N + n0 + c4);
            __half2* d = (__half2*)(Bs + r * 72 + c4);
            d[0] = __floats2half2_rn(v.x, v.y);
            d[1] = __floats2half2_rn(v.z, v.w);
        }
        __syncthreads();
#pragma unroll
        for (int kk = 0; kk < 32; kk += 16) {
            wmma::fragment<wmma::matrix_a, 16, 16, 16, __half, wmma::row_major> af[2];
            wmma::fragment<wmma::matrix_b, 16, 16, 16, __half, wmma::row_major> bf[2];
#pragma unroll
            for (int i = 0; i < 2; i++)
                wmma::load_matrix_sync(af[i], As + (wm * 32 + i * 16) * 48 + kk, 48);
#pragma unroll
            for (int j = 0; j < 2; j++)
                wmma::load_matrix_sync(bf[j], Bs + kk * 72 + wn * 32 + j * 16, 72);
#pragma unroll
            for (int i = 0; i < 2; i++)
#pragma unroll
                for (int j = 0; j < 2; j++)
                    wmma::mma_sync(acc[i][j], af[i], bf[j], acc[i][j]);
        }
        __syncthreads();
    }

    // write accumulators to shared (reuse buffer), then epilogue
#pragma unroll
    for (int i = 0; i < 2; i++)
#pragma unroll
        for (int j = 0; j < 2; j++)
            wmma::store_matrix_sync(Cs + (wm * 32 + i * 16) * 68 + wn * 32 + j * 16,
                                    acc[i][j], 68, wmma::mem_row_major);
    __syncthreads();

#pragma unroll
    for (int l = 0; l < 32; l++) {
        int i = tid + l * 256;          // 8192 = 128x64
        int r = i >> 6, c = i & 63;
        float v = Cs[r * 68 + c];
        int R = m0 + r;
        if (MODE == 0) {
            float rl = fmaxf(v, 0.f);
            g_ActS[(size_t)R * SH_I + n0 + c] = __float2half(rl * rl);
        }
        if (MODE == 1) {
            out[(size_t)R * HID + n0 + c] = v;
        }
        if (MODE == 2) {
            float rl = fmaxf(v, 0.f);
            g_Act[(size_t)R * MOE_I + n0 + c] = __float2half(rl * rl * g_pw[R]);
        }
        if (MODE == 3) {
            int t = g_perm[R];
            atomicAdd(out + (size_t)t * HID + n0 + c, v);
        }
    }
}

// ---------------- launch ----------------
extern "C" void kernel_launch(void* const* d_in, const int* in_sizes, int n_in,
                              void* d_out, int out_size)
{
    const float* x  = (const float*)d_in[0];
    const float* wr = (const float*)d_in[1];
    const float* eb = (const float*)d_in[2];
    const float* wu = (const float*)d_in[3];
    const float* wd = (const float*)d_in[4];
    const float* su = (const float*)d_in[5];
    const float* sd = (const float*)d_in[6];
    float* out = (float*)d_out;

    router_kernel<<<T_TOK / 4, 128>>>(x, wr, eb);
    scan_kernel<<<1, 32>>>();
    gather_kernel<<<NEXP, 256>>>();
    convx_kernel<<<T_TOK, 256>>>(x);
    gatherx_kernel<<<MAX_ROWS, 256>>>(x);

    // shared expert
    gemm_kernel<0><<<dim3(SH_I / 64, T_TOK / 128), 256>>>(su, out);
    gemm_kernel<1><<<dim3(HID / 64, T_TOK / 128), 256>>>(sd, out);
    // routed experts
    gemm_kernel<2><<<dim3(MOE_I / 64, MAX_TILES), 256>>>(wu, out);
    gemm_kernel<3><<<dim3(HID / 64, MAX_TILES), 256>>>(wd, out);
}

// round 5
// speedup vs baseline: 1.4208x; 1.4208x over previous
#include <cuda_runtime.h>
#include <cuda_fp16.h>
#include <mma.h>
#include <math.h>

using namespace nvcuda;

// ---------------- static config ----------------
#define T_TOK   2048
#define HID     2048
#define MOE_I   1024
#define SH_I    4096
#define NEXP    16
#define MAX_TILES 48              // worst-case sum of ceil(cnt_e/128) is 47
#define MAX_ROWS (MAX_TILES*128)

// ---------------- device scratch ----------------
__device__ int    g_topk_idx[T_TOK*2];
__device__ float  g_topk_w[T_TOK*2];
__device__ int    g_off[NEXP];
__device__ int    g_ntiles;
__device__ int    g_tileE[MAX_TILES];
__device__ int    g_tileM0[MAX_TILES];
__device__ int    g_perm[MAX_ROWS];
__device__ float  g_pw[MAX_ROWS];
__device__ __half g_X16[(size_t)T_TOK*HID];
__device__ __half g_XG[(size_t)MAX_ROWS*HID];
__device__ __half g_Act[(size_t)MAX_ROWS*MOE_I];
__device__ __half g_ActS[(size_t)T_TOK*SH_I];
// fp16 weights (converted once per launch)
__device__ __half g_wu16[(size_t)NEXP*HID*MOE_I];
__device__ __half g_wd16[(size_t)NEXP*MOE_I*HID];
__device__ __half g_su16[(size_t)HID*SH_I];
__device__ __half g_sd16[(size_t)SH_I*HID];

// ---------------- fp32 -> fp16 weight conversion ----------------
__global__ __launch_bounds__(256) void cvtw_kernel(const float* __restrict__ src,
                                                   __half* __restrict__ dst, int n8)
{
    int i = blockIdx.x * 256 + threadIdx.x;
    if (i >= n8) return;
    const float4* s = (const float4*)src + (size_t)i * 2;
    float4 a = s[0], b = s[1];
    __half2 h[4];
    h[0] = __floats2half2_rn(a.x, a.y);
    h[1] = __floats2half2_rn(a.z, a.w);
    h[2] = __floats2half2_rn(b.x, b.y);
    h[3] = __floats2half2_rn(b.z, b.w);
    *(uint4*)(dst + (size_t)i * 8) = *(uint4*)h;
}

// ---------------- router (fp32, exact replica of reference routing) ----------------
__global__ __launch_bounds__(128) void router_kernel(
    const float* __restrict__ x, const float* __restrict__ wr,
    const float* __restrict__ eb)
{
    int warp = threadIdx.x >> 5;
    int lane = threadIdx.x & 31;
    int t = blockIdx.x * 4 + warp;
    const float* xr = x + (size_t)t * HID;

    float xv[64];
#pragma unroll
    for (int i = 0; i < 64; i++) xv[i] = xr[lane + 32 * i];

    float sc[NEXP];
#pragma unroll
    for (int e = 0; e < NEXP; e++) {
        const float* w = wr + (size_t)e * HID;
        float s = 0.f;
#pragma unroll
        for (int i = 0; i < 64; i++) s += xv[i] * w[lane + 32 * i];
#pragma unroll
        for (int o = 16; o > 0; o >>= 1) s += __shfl_xor_sync(0xffffffffu, s, o);
        sc[e] = s;
    }

    if (lane == 0) {
        float raw[NEXP], sb[NEXP];
#pragma unroll
        for (int e = 0; e < NEXP; e++) {
            raw[e] = 1.f / (1.f + expf(-sc[e]));
            sb[e]  = raw[e] + eb[e];
        }
        float gs[4];
#pragma unroll
        for (int g = 0; g < 4; g++) {
            float m1 = -1e30f, m2 = -1e30f;
#pragma unroll
            for (int j = 0; j < 4; j++) {
                float v = sb[4 * g + j];
                if (v > m1) { m2 = m1; m1 = v; }
                else if (v > m2) m2 = v;
            }
            gs[g] = m1 + m2;
        }
        int g1 = 0;
        for (int g = 1; g < 4; g++) if (gs[g] > gs[g1]) g1 = g;
        int g2 = -1;
        for (int g = 0; g < 4; g++) if (g != g1 && (g2 < 0 || gs[g] > gs[g2])) g2 = g;
        float masked[NEXP];
#pragma unroll
        for (int e = 0; e < NEXP; e++) {
            int grp = e >> 2;
            masked[e] = (grp == g1 || grp == g2) ? sb[e] : 0.f;
        }
        int e1 = 0;
        for (int e = 1; e < NEXP; e++) if (masked[e] > masked[e1]) e1 = e;
        int e2 = -1;
        for (int e = 0; e < NEXP; e++) if (e != e1 && (e2 < 0 || masked[e] > masked[e2])) e2 = e;

        float w1 = raw[e1], w2 = raw[e2];
        float s = w1 + w2 + 1e-20f;
        g_topk_idx[t * 2 + 0] = e1;
        g_topk_idx[t * 2 + 1] = e2;
        g_topk_w[t * 2 + 0]   = w1 / s;
        g_topk_w[t * 2 + 1]   = w2 / s;
    }
}

// ---------------- scan: counts, padded offsets, tile table ----------------
__global__ void scan_kernel()
{
    __shared__ int cnt[NEXP];
    int e = threadIdx.x;
    if (e < NEXP) {
        int c = 0;
        for (int i = 0; i < T_TOK * 2; i++) c += (g_topk_idx[i] == e);
        cnt[e] = c;
    }
    __syncthreads();
    if (threadIdx.x == 0) {
        int off = 0, nt = 0;
        for (int ee = 0; ee < NEXP; ee++) {
            g_off[ee] = off;
            int tiles = (cnt[ee] + 127) / 128;
            for (int tt = 0; tt < tiles; tt++) {
                g_tileE[nt]  = ee;
                g_tileM0[nt] = off + tt * 128;
                nt++;
            }
            off += tiles * 128;
        }
        g_ntiles = nt;
        for (int i = nt; i < MAX_TILES; i++) { g_tileE[i] = -1; g_tileM0[i] = 0; }
    }
}

// ---------------- gather: deterministic ordered compaction per expert ----------------
__global__ __launch_bounds__(256) void gather_kernel()
{
    int e = blockIdx.x;
    int base = g_off[e];
    int tid = threadIdx.x, lane = tid & 31, wid = tid >> 5;
    __shared__ int warpTot[8];
    int written = 0;

    for (int chunk = 0; chunk < T_TOK; chunk += 256) {
        int t = chunk + tid;
        int i0 = g_topk_idx[t * 2], i1 = g_topk_idx[t * 2 + 1];
        int which = (i0 == e) ? 0 : ((i1 == e) ? 1 : -1);
        unsigned b = __ballot_sync(0xffffffffu, which >= 0);
        int wpre = __popc(b & ((1u << lane) - 1));
        if (lane == 0) warpTot[wid] = __popc(b);
        __syncthreads();
        int woff = 0;
        for (int w = 0; w < wid; w++) woff += warpTot[w];
        if (which >= 0) {
            int pos = base + written + woff + wpre;
            g_perm[pos] = t;
            g_pw[pos]   = g_topk_w[t * 2 + which];
        }
        int tot = 0;
        for (int w = 0; w < 8; w++) tot += warpTot[w];
        written += tot;
        __syncthreads();
    }
    int padEnd = base + ((written + 127) / 128) * 128;
    for (int i = base + written + tid; i < padEnd; i += 256) {
        g_perm[i] = 0;
        g_pw[i]   = 0.f;
    }
}

// ---------------- token fp32->fp16 and gather (fp16 source) ----------------
__global__ __launch_bounds__(256) void convx_kernel(const float* __restrict__ x)
{
    int row = blockIdx.x;
    int c0 = threadIdx.x * 8;
    const float* src = x + (size_t)row * HID + c0;
    float4 a = *(const float4*)src;
    float4 b = *(const float4*)(src + 4);
    __half2 h[4];
    h[0] = __floats2half2_rn(a.x, a.y);
    h[1] = __floats2half2_rn(a.z, a.w);
    h[2] = __floats2half2_rn(b.x, b.y);
    h[3] = __floats2half2_rn(b.z, b.w);
    *(uint4*)(g_X16 + (size_t)row * HID + c0) = *(uint4*)h;
}

__global__ __launch_bounds__(256) void gatherx_kernel()
{
    int row = blockIdx.x;
    int t = g_perm[row];
    int c0 = threadIdx.x * 8;
    *(uint4*)(g_XG + (size_t)row * HID + c0) =
        *(const uint4*)(g_X16 + (size_t)t * HID + c0);
}

// ---------------- pipelined wmma GEMM ----------------
// MODE 0: shared up   : X16  x su16 -> relu^2 -> ActS
// MODE 1: shared down : ActS x sd16 -> out (store)
// MODE 2: routed up   : XG   x wu16[e] -> relu^2 * pw -> Act
// MODE 3: routed down : Act  x wd16[e] -> atomicAdd out
#define BM 128
#define BN 128
#define BK 64
#define STAGES 3
#define A_PITCH 72
#define B_PITCH 136
#define A_ST_HALVES (BM * A_PITCH)                 // 9216
#define B_ST_HALVES (BK * B_PITCH)                 // 8704
#define STAGE_HALVES (A_ST_HALVES + B_ST_HALVES)   // 17920
#define GEMM_SMEM_BYTES (STAGES * STAGE_HALVES * 2) // 107520

__device__ __forceinline__ void cp16(__half* smem, const __half* gmem)
{
    unsigned s = (unsigned)__cvta_generic_to_shared(smem);
    asm volatile("cp.async.cg.shared.global [%0], [%1], 16;\n" :: "r"(s), "l"(gmem));
}

template<int MODE>
__global__ __launch_bounds__(256) void gemm_kernel(const __half* __restrict__ Wb,
                                                   float* __restrict__ out)
{
    constexpr int K = (MODE == 0 || MODE == 2) ? 2048 : (MODE == 1 ? 4096 : 1024);
    constexpr int N = (MODE == 0) ? 4096 : (MODE == 2 ? 1024 : 2048);
    constexpr int KT = K / BK;

    int m0;
    const __half* Bg;
    if (MODE == 2 || MODE == 3) {
        int tile = blockIdx.y;
        if (tile >= g_ntiles) return;
        m0 = g_tileM0[tile];
        Bg = Wb + (size_t)g_tileE[tile] * HID * MOE_I;
    } else {
        m0 = blockIdx.y * BM;
        Bg = Wb;
    }
    int n0 = blockIdx.x * BN;

    const __half* Ag;
    if (MODE == 0) Ag = g_X16 + (size_t)m0 * K;
    if (MODE == 1) Ag = g_ActS + (size_t)m0 * K;
    if (MODE == 2) Ag = g_XG  + (size_t)m0 * K;
    if (MODE == 3) Ag = g_Act + (size_t)m0 * K;

    extern __shared__ __align__(16) char smem[];
    __half* sh = (__half*)smem;

    int tid = threadIdx.x;
    int wid = tid >> 5, wm = wid >> 2, wn = wid & 3; // 2x4 warp grid, 64x32 per warp

    wmma::fragment<wmma::accumulator, 16, 16, 16, float> acc[4][2];
#pragma unroll
    for (int i = 0; i < 4; i++)
#pragma unroll
        for (int j = 0; j < 2; j++) wmma::fill_fragment(acc[i][j], 0.f);

    auto load_stage = [&](int s, int k0) {
        __half* As = sh + s * STAGE_HALVES;
        __half* Bs = As + A_ST_HALVES;
        // A: 128 rows x 64 halves = 1024 x 16B chunks  (FIXED: was l<2 -> rows 64..127 never loaded)
#pragma unroll
        for (int l = 0; l < 4; l++) {
            int i = tid + l * 256;
            int r = i >> 3, c8 = (i & 7) * 8;
            cp16(As + r * A_PITCH + c8, Ag + (size_t)r * K + k0 + c8);
        }
        // B: 64 rows x 128 halves = 1024 x 16B chunks
#pragma unroll
        for (int l = 0; l < 4; l++) {
            int i = tid + l * 256;
            int r = i >> 4, c8 = (i & 15) * 8;
            cp16(Bs + r * B_PITCH + c8, Bg + (size_t)(k0 + r) * N + n0 + c8);
        }
        asm volatile("cp.async.commit_group;\n");
    };

    load_stage(0, 0);
    load_stage(1, BK);

    for (int kt = 0; kt < KT; kt++) {
        if (kt + 2 < KT) {
            asm volatile("cp.async.wait_group 1;\n");
        } else {
            asm volatile("cp.async.wait_group 0;\n");
        }
        __syncthreads();
        if (kt + 2 < KT) load_stage((kt + 2) % STAGES, (kt + 2) * BK);

        __half* As = sh + (kt % STAGES) * STAGE_HALVES;
        __half* Bs = As + A_ST_HALVES;
#pragma unroll
        for (int kk = 0; kk < BK; kk += 16) {
            wmma::fragment<wmma::matrix_a, 16, 16, 16, __half, wmma::row_major> af[4];
            wmma::fragment<wmma::matrix_b, 16, 16, 16, __half, wmma::row_major> bf[2];
#pragma unroll
            for (int i = 0; i < 4; i++)
                wmma::load_matrix_sync(af[i], As + (wm * 64 + i * 16) * A_PITCH + kk, A_PITCH);
#pragma unroll
            for (int j = 0; j < 2; j++)
                wmma::load_matrix_sync(bf[j], Bs + kk * B_PITCH + wn * 32 + j * 16, B_PITCH);
#pragma unroll
            for (int i = 0; i < 4; i++)
#pragma unroll
                for (int j = 0; j < 2; j++)
                    wmma::mma_sync(acc[i][j], af[i], bf[j], acc[i][j]);
        }
        __syncthreads();
    }

    // epilogue via shared (reuse pipeline smem)
    float* Cs = (float*)smem;
#pragma unroll
    for (int i = 0; i < 4; i++)
#pragma unroll
        for (int j = 0; j < 2; j++)
            wmma::store_matrix_sync(Cs + (wm * 64 + i * 16) * 132 + wn * 32 + j * 16,
                                    acc[i][j], 132, wmma::mem_row_major);
    __syncthreads();

#pragma unroll
    for (int l = 0; l < 64; l++) {
        int i = tid + l * 256;          // 16384 = 128x128
        int r = i >> 7, c = i & 127;
        float v = Cs[r * 132 + c];
        int R = m0 + r;
        if (MODE == 0) {
            float rl = fmaxf(v, 0.f);
            g_ActS[(size_t)R * SH_I + n0 + c] = __float2half(rl * rl);
        }
        if (MODE == 1) {
            out[(size_t)R * HID + n0 + c] = v;
        }
        if (MODE == 2) {
            float rl = fmaxf(v, 0.f);
            g_Act[(size_t)R * MOE_I + n0 + c] = __float2half(rl * rl * g_pw[R]);
        }
        if (MODE == 3) {
            atomicAdd(out + (size_t)g_perm[R] * HID + n0 + c, v);
        }
    }
}

// ---------------- launch ----------------
extern "C" void kernel_launch(void* const* d_in, const int* in_sizes, int n_in,
                              void* d_out, int out_size)
{
    const float* x  = (const float*)d_in[0];
    const float* wr = (const float*)d_in[1];
    const float* eb = (const float*)d_in[2];
    const float* wu = (const float*)d_in[3];
    const float* wd = (const float*)d_in[4];
    const float* su = (const float*)d_in[5];
    const float* sd = (const float*)d_in[6];
    float* out = (float*)d_out;

    cudaFuncSetAttribute(gemm_kernel<0>, cudaFuncAttributeMaxDynamicSharedMemorySize, GEMM_SMEM_BYTES);
    cudaFuncSetAttribute(gemm_kernel<1>, cudaFuncAttributeMaxDynamicSharedMemorySize, GEMM_SMEM_BYTES);
    cudaFuncSetAttribute(gemm_kernel<2>, cudaFuncAttributeMaxDynamicSharedMemorySize, GEMM_SMEM_BYTES);
    cudaFuncSetAttribute(gemm_kernel<3>, cudaFuncAttributeMaxDynamicSharedMemorySize, GEMM_SMEM_BYTES);

    __half* wu16p; cudaGetSymbolAddress((void**)&wu16p, g_wu16);
    __half* wd16p; cudaGetSymbolAddress((void**)&wd16p, g_wd16);
    __half* su16p; cudaGetSymbolAddress((void**)&su16p, g_su16);
    __half* sd16p; cudaGetSymbolAddress((void**)&sd16p, g_sd16);

    // weight conversions (fp32 -> fp16)
    cvtw_kernel<<<16384, 256>>>(wu, wu16p, NEXP * HID * MOE_I / 8);
    cvtw_kernel<<<16384, 256>>>(wd, wd16p, NEXP * MOE_I * HID / 8);
    cvtw_kernel<<<4096, 256>>>(su, su16p, HID * SH_I / 8);
    cvtw_kernel<<<4096, 256>>>(sd, sd16p, SH_I * HID / 8);

    // routing + gathers
    router_kernel<<<T_TOK / 4, 128>>>(x, wr, eb);
    scan_kernel<<<1, 32>>>();
    gather_kernel<<<NEXP, 256>>>();
    convx_kernel<<<T_TOK, 256>>>(x);
    gatherx_kernel<<<MAX_ROWS, 256>>>();

    // shared expert
    gemm_kernel<0><<<dim3(SH_I / BN, T_TOK / BM), 256, GEMM_SMEM_BYTES>>>(su16p, out);
    gemm_kernel<1><<<dim3(HID / BN, T_TOK / BM), 256, GEMM_SMEM_BYTES>>>(sd16p, out);
    // routed experts
    gemm_kernel<2><<<dim3(MOE_I / BN, MAX_TILES), 256, GEMM_SMEM_BYTES>>>(wu16p, out);
    gemm_kernel<3><<<dim3(HID / BN, MAX_TILES), 256, GEMM_SMEM_BYTES>>>(wd16p, out);
}

// round 7
// speedup vs baseline: 1.4279x; 1.0050x over previous
#include <cuda_runtime.h>
#include <cuda_fp16.h>
#include <mma.h>
#include <math.h>

using namespace nvcuda;

// ---------------- static config ----------------
#define T_TOK   2048
#define HID     2048
#define MOE_I   1024
#define SH_I    4096
#define NEXP    16
#define MAX_TILES 48
#define MAX_ROWS (MAX_TILES*128)

// ---------------- device scratch ----------------
__device__ int    g_topk_idx[T_TOK*2];
__device__ float  g_topk_w[T_TOK*2];
__device__ int    g_off[NEXP];
__device__ int    g_ntiles;
__device__ int    g_tileE[MAX_TILES];
__device__ int    g_tileM0[MAX_TILES];
__device__ int    g_perm[MAX_ROWS];
__device__ float  g_pw[MAX_ROWS];
__device__ __half g_X16[(size_t)T_TOK*HID];
__device__ __half g_XG[(size_t)MAX_ROWS*HID];
__device__ __half g_Act[(size_t)MAX_ROWS*MOE_I];
__device__ __half g_ActS[(size_t)T_TOK*SH_I];
__device__ __half g_wu16[(size_t)NEXP*HID*MOE_I];
__device__ __half g_wd16[(size_t)NEXP*MOE_I*HID];
__device__ __half g_su16[(size_t)HID*SH_I];
__device__ __half g_sd16[(size_t)SH_I*HID];

// ---------------- fp32 -> fp16 weight conversion (layout preserved [K,N]) ----------------
__global__ __launch_bounds__(256) void cvtw_kernel(const float* __restrict__ src,
                                                   __half* __restrict__ dst, int n8)
{
    int i = blockIdx.x * 256 + threadIdx.x;
    if (i >= n8) return;
    const float4* s = (const float4*)src + (size_t)i * 2;
    float4 a = s[0], b = s[1];
    __half2 h[4];
    h[0] = __floats2half2_rn(a.x, a.y);
    h[1] = __floats2half2_rn(a.z, a.w);
    h[2] = __floats2half2_rn(b.x, b.y);
    h[3] = __floats2half2_rn(b.z, b.w);
    *(uint4*)(dst + (size_t)i * 8) = *(uint4*)h;
}

// ---------------- router (fp32, exact replica of reference routing) ----------------
__global__ __launch_bounds__(128) void router_kernel(
    const float* __restrict__ x, const float* __restrict__ wr,
    const float* __restrict__ eb)
{
    int warp = threadIdx.x >> 5;
    int lane = threadIdx.x & 31;
    int t = blockIdx.x * 4 + warp;
    const float* xr = x + (size_t)t * HID;

    float xv[64];
#pragma unroll
    for (int i = 0; i < 64; i++) xv[i] = xr[lane + 32 * i];

    float sc[NEXP];
#pragma unroll
    for (int e = 0; e < NEXP; e++) {
        const float* w = wr + (size_t)e * HID;
        float s = 0.f;
#pragma unroll
        for (int i = 0; i < 64; i++) s += xv[i] * w[lane + 32 * i];
#pragma unroll
        for (int o = 16; o > 0; o >>= 1) s += __shfl_xor_sync(0xffffffffu, s, o);
        sc[e] = s;
    }

    if (lane == 0) {
        float raw[NEXP], sb[NEXP];
#pragma unroll
        for (int e = 0; e < NEXP; e++) {
            raw[e] = 1.f / (1.f + expf(-sc[e]));
            sb[e]  = raw[e] + eb[e];
        }
        float gs[4];
#pragma unroll
        for (int g = 0; g < 4; g++) {
            float m1 = -1e30f, m2 = -1e30f;
#pragma unroll
            for (int j = 0; j < 4; j++) {
                float v = sb[4 * g + j];
                if (v > m1) { m2 = m1; m1 = v; }
                else if (v > m2) m2 = v;
            }
            gs[g] = m1 + m2;
        }
        int g1 = 0;
        for (int g = 1; g < 4; g++) if (gs[g] > gs[g1]) g1 = g;
        int g2 = -1;
        for (int g = 0; g < 4; g++) if (g != g1 && (g2 < 0 || gs[g] > gs[g2])) g2 = g;
        float masked[NEXP];
#pragma unroll
        for (int e = 0; e < NEXP; e++) {
            int grp = e >> 2;
            masked[e] = (grp == g1 || grp == g2) ? sb[e] : 0.f;
        }
        int e1 = 0;
        for (int e = 1; e < NEXP; e++) if (masked[e] > masked[e1]) e1 = e;
        int e2 = -1;
        for (int e = 0; e < NEXP; e++) if (e != e1 && (e2 < 0 || masked[e] > masked[e2])) e2 = e;

        float w1 = raw[e1], w2 = raw[e2];
        float s = w1 + w2 + 1e-20f;
        g_topk_idx[t * 2 + 0] = e1;
        g_topk_idx[t * 2 + 1] = e2;
        g_topk_w[t * 2 + 0]   = w1 / s;
        g_topk_w[t * 2 + 1]   = w2 / s;
    }
}

// ---------------- scan ----------------
__global__ void scan_kernel()
{
    __shared__ int cnt[NEXP];
    int e = threadIdx.x;
    if (e < NEXP) {
        int c = 0;
        for (int i = 0; i < T_TOK * 2; i++) c += (g_topk_idx[i] == e);
        cnt[e] = c;
    }
    __syncthreads();
    if (threadIdx.x == 0) {
        int off = 0, nt = 0;
        for (int ee = 0; ee < NEXP; ee++) {
            g_off[ee] = off;
            int tiles = (cnt[ee] + 127) / 128;
            for (int tt = 0; tt < tiles; tt++) {
                g_tileE[nt]  = ee;
                g_tileM0[nt] = off + tt * 128;
                nt++;
            }
            off += tiles * 128;
        }
        g_ntiles = nt;
        for (int i = nt; i < MAX_TILES; i++) { g_tileE[i] = -1; g_tileM0[i] = 0; }
    }
}

// ---------------- gather ----------------
__global__ __launch_bounds__(256) void gather_kernel()
{
    int e = blockIdx.x;
    int base = g_off[e];
    int tid = threadIdx.x, lane = tid & 31, wid = tid >> 5;
    __shared__ int warpTot[8];
    int written = 0;

    for (int chunk = 0; chunk < T_TOK; chunk += 256) {
        int t = chunk + tid;
        int i0 = g_topk_idx[t * 2], i1 = g_topk_idx[t * 2 + 1];
        int which = (i0 == e) ? 0 : ((i1 == e) ? 1 : -1);
        unsigned b = __ballot_sync(0xffffffffu, which >= 0);
        int wpre = __popc(b & ((1u << lane) - 1));
        if (lane == 0) warpTot[wid] = __popc(b);
        __syncthreads();
        int woff = 0;
        for (int w = 0; w < wid; w++) woff += warpTot[w];
        if (which >= 0) {
            int pos = base + written + woff + wpre;
            g_perm[pos] = t;
            g_pw[pos]   = g_topk_w[t * 2 + which];
        }
        int tot = 0;
        for (int w = 0; w < 8; w++) tot += warpTot[w];
        written += tot;
        __syncthreads();
    }
    int padEnd = base + ((written + 127) / 128) * 128;
    for (int i = base + written + tid; i < padEnd; i += 256) {
        g_perm[i] = 0;
        g_pw[i]   = 0.f;
    }
}

// ---------------- token fp32->fp16 and gather ----------------
__global__ __launch_bounds__(256) void convx_kernel(const float* __restrict__ x)
{
    int row = blockIdx.x;
    int c0 = threadIdx.x * 8;
    const float* src = x + (size_t)row * HID + c0;
    float4 a = *(const float4*)src;
    float4 b = *(const float4*)(src + 4);
    __half2 h[4];
    h[0] = __floats2half2_rn(a.x, a.y);
    h[1] = __floats2half2_rn(a.z, a.w);
    h[2] = __floats2half2_rn(b.x, b.y);
    h[3] = __floats2half2_rn(b.z, b.w);
    *(uint4*)(g_X16 + (size_t)row * HID + c0) = *(uint4*)h;
}

__global__ __launch_bounds__(256) void gatherx_kernel()
{
    int row = blockIdx.x;
    int t = g_perm[row];
    int c0 = threadIdx.x * 8;
    *(uint4*)(g_XG + (size_t)row * HID + c0) =
        *(const uint4*)(g_X16 + (size_t)t * HID + c0);
}

// ---------------- pipelined wmma GEMM: 4 warps, 64x64 warp tiles ----------------
// MODE 0: shared up   : X16  x su16 -> relu^2 -> ActS
// MODE 1: shared down : ActS x sd16 -> out (store)
// MODE 2: routed up   : XG   x wu16[e] -> relu^2 * pw -> Act
// MODE 3: routed down : Act  x wd16[e] -> atomicAdd out
#define BM 128
#define BN 128
#define BK 32
#define STAGES 4
#define A_PITCH 40                                  // 32 + 8 halves
#define B_PITCH 136                                 // 128 + 8 halves
#define A_ST_HALVES (BM * A_PITCH)                  // 5120
#define B_ST_HALVES (BK * B_PITCH)                  // 4352
#define STAGE_HALVES (A_ST_HALVES + B_ST_HALVES)    // 9472
#define GEMM_SMEM_BYTES (STAGES * STAGE_HALVES * 2) // 75776

__device__ __forceinline__ void cp16(__half* smem, const __half* gmem)
{
    unsigned s = (unsigned)__cvta_generic_to_shared(smem);
    asm volatile("cp.async.cg.shared.global [%0], [%1], 16;\n" :: "r"(s), "l"(gmem));
}

template<int MODE>
__global__ __launch_bounds__(128) void gemm_kernel(const __half* __restrict__ Wb,
                                                   float* __restrict__ out)
{
    constexpr int K = (MODE == 0 || MODE == 2) ? 2048 : (MODE == 1 ? 4096 : 1024);
    constexpr int N = (MODE == 0) ? 4096 : (MODE == 2 ? 1024 : 2048);
    constexpr int KT = K / BK;

    int m0;
    const __half* Bg;
    if (MODE == 2 || MODE == 3) {
        int tile = blockIdx.y;
        if (tile >= g_ntiles) return;
        m0 = g_tileM0[tile];
        Bg = Wb + (size_t)g_tileE[tile] * HID * MOE_I;
    } else {
        m0 = blockIdx.y * BM;
        Bg = Wb;
    }
    int n0 = blockIdx.x * BN;

    const __half* Ag;
    if (MODE == 0) Ag = g_X16 + (size_t)m0 * K;
    if (MODE == 1) Ag = g_ActS + (size_t)m0 * K;
    if (MODE == 2) Ag = g_XG  + (size_t)m0 * K;
    if (MODE == 3) Ag = g_Act + (size_t)m0 * K;

    extern __shared__ __align__(16) char smem[];
    __half* sh = (__half*)smem;

    int tid = threadIdx.x;
    int wid = tid >> 5;
    int wm = wid >> 1, wn = wid & 1;   // 2x2 warp grid, 64x64 per warp

    wmma::fragment<wmma::accumulator, 16, 16, 16, float> acc[4][4];
#pragma unroll
    for (int i = 0; i < 4; i++)
#pragma unroll
        for (int j = 0; j < 4; j++) wmma::fill_fragment(acc[i][j], 0.f);

    auto load_stage = [&](int s, int k0) {
        __half* As = sh + s * STAGE_HALVES;
        __half* Bs = As + A_ST_HALVES;
        // A: 128 rows x 32 halves = 512 x 16B chunks
#pragma unroll
        for (int l = 0; l < 4; l++) {
            int i = tid + l * 128;
            int r = i >> 2, c8 = (i & 3) * 8;
            cp16(As + r * A_PITCH + c8, Ag + (size_t)r * K + k0 + c8);
        }
        // B: 32 rows x 128 halves = 512 x 16B chunks
#pragma unroll
        for (int l = 0; l < 4; l++) {
            int i = tid + l * 128;
            int r = i >> 4, c8 = (i & 15) * 8;
            cp16(Bs + r * B_PITCH + c8, Bg + (size_t)(k0 + r) * N + n0 + c8);
        }
        asm volatile("cp.async.commit_group;\n");
    };

    load_stage(0, 0);
    load_stage(1, BK);
    load_stage(2, 2 * BK);

    for (int kt = 0; kt < KT; kt++) {
        if (kt + 3 < KT) asm volatile("cp.async.wait_group 2;\n");
        else if (kt + 2 < KT) asm volatile("cp.async.wait_group 1;\n");
        else asm volatile("cp.async.wait_group 0;\n");
        __syncthreads();
        if (kt + 3 < KT) load_stage((kt + 3) % STAGES, (kt + 3) * BK);

        __half* As = sh + (kt % STAGES) * STAGE_HALVES;
        __half* Bs = As + A_ST_HALVES;
#pragma unroll
        for (int kk = 0; kk < BK; kk += 16) {
            wmma::fragment<wmma::matrix_a, 16, 16, 16, __half, wmma::row_major> af[4];
            wmma::fragment<wmma::matrix_b, 16, 16, 16, __half, wmma::row_major> bf[4];
#pragma unroll
            for (int i = 0; i < 4; i++)
                wmma::load_matrix_sync(af[i], As + (wm * 64 + i * 16) * A_PITCH + kk, A_PITCH);
#pragma unroll
            for (int j = 0; j < 4; j++)
                wmma::load_matrix_sync(bf[j], Bs + kk * B_PITCH + wn * 64 + j * 16, B_PITCH);
#pragma unroll
            for (int i = 0; i < 4; i++)
#pragma unroll
                for (int j = 0; j < 4; j++)
                    wmma::mma_sync(acc[i][j], af[i], bf[j], acc[i][j]);
        }
        __syncthreads();
    }

    // epilogue via shared (reuse pipeline smem)
    float* Cs = (float*)smem;
#pragma unroll
    for (int i = 0; i < 4; i++)
#pragma unroll
        for (int j = 0; j < 4; j++)
            wmma::store_matrix_sync(Cs + (wm * 64 + i * 16) * 132 + wn * 64 + j * 16,
                                    acc[i][j], 132, wmma::mem_row_major);
    __syncthreads();

#pragma unroll
    for (int l = 0; l < 128; l++) {
        int i = tid + l * 128;          // 16384 = 128x128
        int r = i >> 7, c = i & 127;
        float v = Cs[r * 132 + c];
        int R = m0 + r;
        if (MODE == 0) {
            float rl = fmaxf(v, 0.f);
            g_ActS[(size_t)R * SH_I + n0 + c] = __float2half(rl * rl);
        }
        if (MODE == 1) {
            out[(size_t)R * HID + n0 + c] = v;
        }
        if (MODE == 2) {
            float rl = fmaxf(v, 0.f);
            g_Act[(size_t)R * MOE_I + n0 + c] = __float2half(rl * rl * g_pw[R]);
        }
        if (MODE == 3) {
            atomicAdd(out + (size_t)g_perm[R] * HID + n0 + c, v);
        }
    }
}

// ---------------- launch ----------------
extern "C" void kernel_launch(void* const* d_in, const int* in_sizes, int n_in,
                              void* d_out, int out_size)
{
    const float* x  = (const float*)d_in[0];
    const float* wr = (const float*)d_in[1];
    const float* eb = (const float*)d_in[2];
    const float* wu = (const float*)d_in[3];
    const float* wd = (const float*)d_in[4];
    const float* su = (const float*)d_in[5];
    const float* sd = (const float*)d_in[6];
    float* out = (float*)d_out;

    cudaFuncSetAttribute(gemm_kernel<0>, cudaFuncAttributeMaxDynamicSharedMemorySize, GEMM_SMEM_BYTES);
    cudaFuncSetAttribute(gemm_kernel<1>, cudaFuncAttributeMaxDynamicSharedMemorySize, GEMM_SMEM_BYTES);
    cudaFuncSetAttribute(gemm_kernel<2>, cudaFuncAttributeMaxDynamicSharedMemorySize, GEMM_SMEM_BYTES);
    cudaFuncSetAttribute(gemm_kernel<3>, cudaFuncAttributeMaxDynamicSharedMemorySize, GEMM_SMEM_BYTES);

    __half* wu16p; cudaGetSymbolAddress((void**)&wu16p, g_wu16);
    __half* wd16p; cudaGetSymbolAddress((void**)&wd16p, g_wd16);
    __half* su16p; cudaGetSymbolAddress((void**)&su16p, g_su16);
    __half* sd16p; cudaGetSymbolAddress((void**)&sd16p, g_sd16);

    // weight conversions (fp32 -> fp16)
    cvtw_kernel<<<16384, 256>>>(wu, wu16p, NEXP * HID * MOE_I / 8);
    cvtw_kernel<<<16384, 256>>>(wd, wd16p, NEXP * MOE_I * HID / 8);
    cvtw_kernel<<<4096, 256>>>(su, su16p, HID * SH_I / 8);
    cvtw_kernel<<<4096, 256>>>(sd, sd16p, SH_I * HID / 8);

    // routing + gathers
    router_kernel<<<T_TOK / 4, 128>>>(x, wr, eb);
    scan_kernel<<<1, 32>>>();
    gather_kernel<<<NEXP, 256>>>();
    convx_kernel<<<T_TOK, 256>>>(x);
    gatherx_kernel<<<MAX_ROWS, 256>>>();

    // shared expert (MODE1 writes out fully before MODE3 atomics)
    gemm_kernel<0><<<dim3(SH_I / BN, T_TOK / BM), 128, GEMM_SMEM_BYTES>>>(su16p, out);
    gemm_kernel<1><<<dim3(HID / BN, T_TOK / BM), 128, GEMM_SMEM_BYTES>>>(sd16p, out);
    // routed experts
    gemm_kernel<2><<<dim3(MOE_I / BN, MAX_TILES), 128, GEMM_SMEM_BYTES>>>(wu16p, out);
    gemm_kernel<3><<<dim3(HID / BN, MAX_TILES), 128, GEMM_SMEM_BYTES>>>(wd16p, out);
}